// round 11
// baseline (speedup 1.0000x reference)
#include <cuda_runtime.h>
#include <math.h>

#define ROWS_PER_CHUNK 4096          // 4 batches * 16 * 64
#define POOL_BLOCKS 512              // 8 rows (warps) per block
#define ADD_BLOCKS 4096              // 1 row per block

// Scratch (allocation-free rule: __device__ globals)
__device__ float g_pooled[16 * 16 * 64];
__device__ float g_delta [16 * 16 * 64];
__device__ int   g_pool_done = 0;    // reset to 0 by mid-block each launch

// ---------------------------------------------------------------------------
// mid math for 4 batches (one chunk), executed by one 256-thread block after
// all pool blocks of this launch have finished (spin on g_pool_done).
// ---------------------------------------------------------------------------
__device__ void mid_for_chunk(int chunk,
                              const float* __restrict__ compress_w,
                              const float* __restrict__ compress_b,
                              const float* __restrict__ in_proj_w,
                              const float* __restrict__ in_proj_b,
                              const float* __restrict__ out_proj_w,
                              const float* __restrict__ out_proj_b,
                              const float* __restrict__ expand_w,
                              const float* __restrict__ expand_b,
                              const float* __restrict__ ln_w,
                              const float* __restrict__ ln_b,
                              const float* __restrict__ gate)
{
    const int tid = threadIdx.x;  // 0..255

    // wait for this launch's pool blocks
    if (tid == 0) {
        volatile int* p = &g_pool_done;
        while (*p < POOL_BLOCKS) { }
        __threadfence();            // acquire pooled values
        g_pool_done = 0;            // reset for next launch (before next launch runs)
        __threadfence();
    }
    __syncthreads();

    __shared__ float sp[16][64];
    __shared__ float sxc[16][4];
    __shared__ float sqkv[16][12];
    __shared__ float so[16][4];
    __shared__ float sat[16][4];
    __shared__ float sy[16][64];

    for (int bb = 0; bb < 4; bb++) {
        const int b = chunk * 4 + bb;

        for (int i = tid; i < 1024; i += 256)
            sp[i >> 6][i & 63] = g_pooled[b * 1024 + i];
        __syncthreads();

        // compress: [16,64] @ [64->4]
        if (tid < 64) {
            const int l = tid >> 2, e = tid & 3;
            float s = compress_b[e];
            #pragma unroll
            for (int j = 0; j < 64; j++) s += sp[l][j] * compress_w[e * 64 + j];
            sxc[l][e] = s;
        }
        __syncthreads();

        // qkv: [16,4] @ [4->12]
        if (tid < 192) {
            const int l = tid / 12, r = tid % 12;
            float s = in_proj_b[r];
            #pragma unroll
            for (int e = 0; e < 4; e++) s += sxc[l][e] * in_proj_w[r * 4 + e];
            sqkv[l][r] = s;
        }
        __syncthreads();

        // attention: 2 heads, dh=2, L=16
        if (tid < 32) {
            const int h = tid >> 4, q = tid & 15;
            const int d0 = h * 2, d1 = h * 2 + 1;
            const float scale = 0.70710678118654752440f;
            float sc[16], m = -1e30f;
            #pragma unroll
            for (int j = 0; j < 16; j++) {
                const float v = (sqkv[q][d0] * sqkv[j][4 + d0] +
                                 sqkv[q][d1] * sqkv[j][4 + d1]) * scale;
                sc[j] = v;
                m = fmaxf(m, v);
            }
            float denom = 0.f;
            #pragma unroll
            for (int j = 0; j < 16; j++) { sc[j] = __expf(sc[j] - m); denom += sc[j]; }
            const float inv = 1.0f / denom;
            float o0 = 0.f, o1 = 0.f;
            #pragma unroll
            for (int j = 0; j < 16; j++) {
                const float a = sc[j] * inv;
                o0 += a * sqkv[j][8 + d0];
                o1 += a * sqkv[j][8 + d1];
            }
            so[q][d0] = o0;
            so[q][d1] = o1;
        }
        __syncthreads();

        // out_proj: [16,4] @ [4->4]
        if (tid < 64) {
            const int l = tid >> 2, e = tid & 3;
            float s = out_proj_b[e];
            #pragma unroll
            for (int j = 0; j < 4; j++) s += so[l][j] * out_proj_w[e * 4 + j];
            sat[l][e] = s;
        }
        __syncthreads();

        // expand + residual + gate
        {
            const float g = gate[0];
            for (int i = tid; i < 1024; i += 256) {
                const int l = i >> 6, c = i & 63;
                float s = expand_b[c];
                #pragma unroll
                for (int j = 0; j < 4; j++) s += sat[l][j] * expand_w[c * 4 + j];
                sy[l][c] = sp[l][c] + g * s;
            }
        }
        __syncthreads();

        // LayerNorm + delta
        if (tid < 16) {
            const int l = tid;
            float mu = 0.f;
            #pragma unroll
            for (int c = 0; c < 64; c++) mu += sy[l][c];
            mu *= (1.0f / 64.0f);
            float var = 0.f;
            #pragma unroll
            for (int c = 0; c < 64; c++) {
                const float d = sy[l][c] - mu;
                var += d * d;
            }
            var *= (1.0f / 64.0f);
            const float inv = rsqrtf(var + 1e-5f);
            #pragma unroll
            for (int c = 0; c < 64; c++) {
                const float o = (sy[l][c] - mu) * inv * ln_w[c] + ln_b[c];
                g_delta[b * 1024 + l * 64 + c] = o - sp[l][c];
            }
        }
        __syncthreads();
    }
}

// ---------------------------------------------------------------------------
// Combined kernel. Grid layout (256 threads per block):
//   pool_chunk >= 0:  bid 0            -> mid block (spins for pool completion)
//                     bid 1..512       -> pool blocks (8 rows each, default-cached)
//                     bid 513..        -> add blocks (row = add_chunk*4096 + bid-513)
//   pool_chunk < 0 :  bid 0..          -> add blocks directly
// ---------------------------------------------------------------------------
__global__ void __launch_bounds__(256)
combined_kernel(const float* __restrict__ x, float* __restrict__ out,
                int pool_chunk, int add_chunk,
                const float* __restrict__ compress_w,
                const float* __restrict__ compress_b,
                const float* __restrict__ in_proj_w,
                const float* __restrict__ in_proj_b,
                const float* __restrict__ out_proj_w,
                const float* __restrict__ out_proj_b,
                const float* __restrict__ expand_w,
                const float* __restrict__ expand_b,
                const float* __restrict__ ln_w,
                const float* __restrict__ ln_b,
                const float* __restrict__ gate)
{
    int bid = blockIdx.x;

    if (pool_chunk >= 0) {
        if (bid == 0) {
            mid_for_chunk(pool_chunk, compress_w, compress_b, in_proj_w, in_proj_b,
                          out_proj_w, out_proj_b, expand_w, expand_b, ln_w, ln_b, gate);
            return;
        }
        if (bid <= POOL_BLOCKS) {
            // ---- pool role: 8 warps, one row each; default-cached loads ----
            const int wid = threadIdx.x >> 5;
            const int lane = threadIdx.x & 31;
            const int row = pool_chunk * ROWS_PER_CHUNK + (bid - 1) * 8 + wid;
            const float4* p = reinterpret_cast<const float4*>(x) + ((size_t)row << 10);
            float s = 0.f;
            #pragma unroll 8
            for (int j = lane; j < 1024; j += 32) {
                const float4 v = p[j];          // default: lines linger in L2
                s += (v.x + v.y) + (v.z + v.w);
            }
            #pragma unroll
            for (int o = 16; o > 0; o >>= 1)
                s += __shfl_down_sync(0xffffffffu, s, o);
            if (lane == 0)
                g_pooled[row] = s * (1.0f / 4096.0f);
            __syncthreads();
            if (threadIdx.x == 0) {
                __threadfence();                 // publish pooled rows
                atomicAdd(&g_pool_done, 1);
            }
            return;
        }
        bid -= (POOL_BLOCKS + 1);
    }

    // ---- add role: one row per block; evict-first reads + streaming stores --
    const int row = add_chunk * ROWS_PER_CHUNK + bid;
    const float d = g_delta[row];
    const size_t base = ((size_t)row << 10) + threadIdx.x;
    const float4* xin = reinterpret_cast<const float4*>(x) + base;
    float4* oo = reinterpret_cast<float4*>(out) + base;

    float4 v0 = __ldcs(xin);
    float4 v1 = __ldcs(xin + 256);
    float4 v2 = __ldcs(xin + 512);
    float4 v3 = __ldcs(xin + 768);

    v0.x += d; v0.y += d; v0.z += d; v0.w += d;
    v1.x += d; v1.y += d; v1.z += d; v1.w += d;
    v2.x += d; v2.y += d; v2.z += d; v2.w += d;
    v3.x += d; v3.y += d; v3.z += d; v3.w += d;

    __stcs(oo,       v0);
    __stcs(oo + 256, v1);
    __stcs(oo + 512, v2);
    __stcs(oo + 768, v3);
}

extern "C" void kernel_launch(void* const* d_in, const int* in_sizes, int n_in,
                              void* d_out, int out_size) {
    const float* x          = (const float*)d_in[0];
    const float* compress_w = (const float*)d_in[1];
    const float* compress_b = (const float*)d_in[2];
    const float* in_proj_w  = (const float*)d_in[3];
    const float* in_proj_b  = (const float*)d_in[4];
    const float* out_proj_w = (const float*)d_in[5];
    const float* out_proj_b = (const float*)d_in[6];
    const float* expand_w   = (const float*)d_in[7];
    const float* expand_b   = (const float*)d_in[8];
    const float* ln_w       = (const float*)d_in[9];
    const float* ln_b       = (const float*)d_in[10];
    const float* gate       = (const float*)d_in[11];
    float* out = (float*)d_out;

#define ARGS compress_w, compress_b, in_proj_w, in_proj_b, out_proj_w, out_proj_b, \
             expand_w, expand_b, ln_w, ln_b, gate

    // L0: pool(0) + mid(0)
    combined_kernel<<<POOL_BLOCKS + 1, 256>>>(x, out, 0, -1, ARGS);
    // L1..L3: add(k-1) overlapped with pool(k)+mid(k)
    for (int k = 1; k < 4; k++)
        combined_kernel<<<POOL_BLOCKS + 1 + ADD_BLOCKS, 256>>>(x, out, k, k - 1, ARGS);
    // L4: add(3)
    combined_kernel<<<ADD_BLOCKS, 256>>>(x, out, -1, 3, ARGS);
#undef ARGS
}